// round 9
// baseline (speedup 1.0000x reference)
#include <cuda_runtime.h>
#include <cuda_fp16.h>
#include <math.h>
#include <stdint.h>

#define Bc 8
#define Tc 2048
#define DMc 1024
#define Hc 8
#define SDc 64
#define INNERc 512
#define HIDc 4096
#define Mrows (Bc * Tc)

typedef __half fp16;

__device__ __align__(256) float g_n  [(size_t)Mrows * DMc];
__device__ __align__(256) fp16  g_nh [(size_t)Mrows * DMc];
__device__ __align__(256) float g_proj[(size_t)Mrows * 2048]; // a|b|ql|qr fused
__device__ __align__(256) float g_sd [(size_t)Mrows * Hc];
__device__ __align__(256) float g_pd [(size_t)Mrows * Hc];
__device__ __align__(256) fp16  g_ys [(size_t)Mrows * INNERc];
__device__ __align__(256) float g_h  [(size_t)Mrows * DMc];
__device__ __align__(256) fp16  g_fin[(size_t)Mrows * DMc];
__device__ __align__(256) fp16  g_mid[(size_t)Mrows * HIDc];
__device__ __align__(256) fp16 g_wp[2048*DMc];
__device__ __align__(256) fp16 g_wo[DMc*INNERc];
__device__ __align__(256) fp16 g_w1[HIDc*DMc];
__device__ __align__(256) fp16 g_w2[DMc*HIDc];

// ---------------- helpers ----------------
__device__ __forceinline__ uint32_t smem_u32(const void* p) {
    return (uint32_t)__cvta_generic_to_shared(p);
}
__device__ __forceinline__ void cp16(uint32_t dst, const void* src) {
    asm volatile("cp.async.cg.shared.global [%0], [%1], 16;\n" :: "r"(dst), "l"(src));
}
__device__ __forceinline__ void cp_commit() { asm volatile("cp.async.commit_group;\n"); }
template <int NN> __device__ __forceinline__ void cp_wait() {
    asm volatile("cp.async.wait_group %0;\n" :: "n"(NN));
}
__device__ __forceinline__ void ldm_x4(uint32_t* r, uint32_t addr) {
    asm volatile("ldmatrix.sync.aligned.m8n8.x4.shared.b16 {%0,%1,%2,%3}, [%4];"
        : "=r"(r[0]), "=r"(r[1]), "=r"(r[2]), "=r"(r[3]) : "r"(addr));
}
__device__ __forceinline__ void mma_fp16(float* d, const uint32_t* a, const uint32_t* b) {
    asm volatile("mma.sync.aligned.m16n8k16.row.col.f32.f16.f16.f32 "
        "{%0,%1,%2,%3},{%4,%5,%6,%7},{%8,%9},{%0,%1,%2,%3};"
        : "+f"(d[0]), "+f"(d[1]), "+f"(d[2]), "+f"(d[3])
        : "r"(a[0]), "r"(a[1]), "r"(a[2]), "r"(a[3]), "r"(b[0]), "r"(b[1]));
}

// ---------------- LN (+optional fp32 out) + fp16 out ----------------
template <bool F32OUT>
__global__ void ln_h_kernel(const float* __restrict__ X,
                            const float* __restrict__ gam,
                            const float* __restrict__ bet,
                            float* __restrict__ Of, fp16* __restrict__ Oh)
{
    int row = blockIdx.x, tid = threadIdx.x;
    const float4* xr = reinterpret_cast<const float4*>(X + (size_t)row * DMc);
    float4 v = xr[tid];
    float s = v.x + v.y + v.z + v.w;
    float q = v.x*v.x + v.y*v.y + v.z*v.z + v.w*v.w;
    int lane = tid & 31, wid = tid >> 5;
#pragma unroll
    for (int o = 16; o; o >>= 1) {
        s += __shfl_xor_sync(0xffffffffu, s, o);
        q += __shfl_xor_sync(0xffffffffu, q, o);
    }
    __shared__ float rs[8], rq[8];
    if (!lane) { rs[wid] = s; rq[wid] = q; }
    __syncthreads();
    if (tid == 0) {
        float S = 0.f, Q = 0.f;
#pragma unroll
        for (int i = 0; i < 8; i++) { S += rs[i]; Q += rq[i]; }
        rs[0] = S; rq[0] = Q;
    }
    __syncthreads();
    float mu = rs[0] * (1.0f / DMc);
    float var = rq[0] * (1.0f / DMc) - mu * mu;
    float rstd = rsqrtf(var + 1e-5f);
    const float4 gg = reinterpret_cast<const float4*>(gam)[tid];
    const float4 bb = reinterpret_cast<const float4*>(bet)[tid];
    float o[4];
    o[0] = (v.x-mu)*rstd*gg.x + bb.x; o[1] = (v.y-mu)*rstd*gg.y + bb.y;
    o[2] = (v.z-mu)*rstd*gg.z + bb.z; o[3] = (v.w-mu)*rstd*gg.w + bb.w;
    size_t off = (size_t)row * DMc + tid * 4;
    if (F32OUT)
        *reinterpret_cast<float4*>(Of + off) = make_float4(o[0], o[1], o[2], o[3]);
    __half2 h0 = __halves2half2(__float2half(o[0]), __float2half(o[1]));
    __half2 h1 = __halves2half2(__float2half(o[2]), __float2half(o[3]));
    *reinterpret_cast<uint2*>(Oh + off) = make_uint2(*(uint32_t*)&h0, *(uint32_t*)&h1);
}

// ---------------- weight transpose: W[K,N] f32 -> [N,K] fp16 ----------------
__global__ void tsplit_kernel(const float* __restrict__ W,
                              fp16* __restrict__ Oh, int K, int N)
{
    __shared__ float t[32][33];
    int n0 = blockIdx.x * 32, k0 = blockIdx.y * 32;
    int tx = threadIdx.x, ty = threadIdx.y;  // 32 x 8
#pragma unroll
    for (int j = 0; j < 32; j += 8)
        t[ty + j][tx] = W[(size_t)(k0 + ty + j) * N + n0 + tx];
    __syncthreads();
#pragma unroll
    for (int j = 0; j < 32; j += 8)
        Oh[(size_t)(n0 + ty + j) * K + k0 + tx] = __float2half(t[tx][ty + j]);
}

// fused: 4 projection weights [1024,512] -> packed [2048,1024]
__global__ void tsplit4_kernel(const float* __restrict__ Wa, const float* __restrict__ Wb,
                               const float* __restrict__ Wql, const float* __restrict__ Wqr,
                               fp16* __restrict__ Oh)
{
    int z = blockIdx.z;
    const float* W = (z == 0) ? Wa : (z == 1) ? Wb : (z == 2) ? Wql : Wqr;
    __shared__ float t[32][33];
    int n0 = blockIdx.x * 32, k0 = blockIdx.y * 32;
    int tx = threadIdx.x, ty = threadIdx.y;
#pragma unroll
    for (int j = 0; j < 32; j += 8)
        t[ty + j][tx] = W[(size_t)(k0 + ty + j) * INNERc + n0 + tx];
    __syncthreads();
#pragma unroll
    for (int j = 0; j < 32; j += 8)
        Oh[(size_t)(z * INNERc + n0 + ty + j) * DMc + k0 + tx] = __float2half(t[tx][ty + j]);
}

// ---------------- mma.sync fp16 GEMM: tile 128x128x64, 3-stage, 1 sync/iter --
enum { EPI_TANH = 1, EPI_RES = 2, EPI_GELU = 3, EPI_RES_BIAS = 4 };
#define LDB 144u           // 64 fp16 = 128B + 16B pad
#define MATB 18432u        // 128 rows * 144B
#define STAGEB 36864u
#define NSTAGE 3
#define SMEM_DYN (3 * 36864)

template <int EPI>
__global__ __launch_bounds__(256)
void mma_gemm(const fp16* __restrict__ A, const fp16* __restrict__ B,
              float* __restrict__ C, fp16* __restrict__ Oh,
              const float* __restrict__ res, const float* __restrict__ bias,
              int M, int N, int K)
{
    extern __shared__ char smraw[];
    uint32_t sbase = smem_u32(smraw);
    int tid = threadIdx.x, lane = tid & 31, wid = tid >> 5;
    int warp_m = wid & 3, warp_n = wid >> 2;
    int bm = blockIdx.y * 128, bn = blockIdx.x * 128;

    float acc[2][8][4];
#pragma unroll
    for (int a = 0; a < 2; a++)
#pragma unroll
        for (int b = 0; b < 8; b++)
#pragma unroll
            for (int c = 0; c < 4; c++) acc[a][b][c] = 0.f;

    auto load_stage = [&](int c) {
        int k0 = c * 64;
        uint32_t st = sbase + (uint32_t)(c % NSTAGE) * STAGEB;
#pragma unroll
        for (int i = 0; i < 8; i++) {
            int id = tid + i * 256;
            int mat = id >> 10, rem = id & 1023;
            int r = rem >> 3, g = rem & 7;
            const fp16* src = mat ? B : A;
            int row = (mat ? bn : bm) + r;
            cp16(st + (uint32_t)mat * MATB + (uint32_t)r * LDB + (uint32_t)g * 16u,
                 src + (size_t)row * K + k0 + g * 8);
        }
        cp_commit();
    };

    int NC = K / 64;
    load_stage(0);
    load_stage(1);

    uint32_t a_off = (uint32_t)(warp_m * 32 + (lane & 15)) * LDB + (uint32_t)((lane >> 4) << 4);
    int bg = lane >> 3, bt = lane & 7;
    uint32_t b_off = (uint32_t)(warp_n * 64 + ((bg >> 1) << 3) + bt) * LDB + (uint32_t)((bg & 1) << 4);

    for (int c = 0; c < NC; c++) {
        cp_wait<1>();          // stage c arrived (c+1 may still be in flight)
        __syncthreads();       // doubles as release of slot (c+2)%3 (stage c-1)
        if (c + 2 < NC) load_stage(c + 2);
        uint32_t st = sbase + (uint32_t)(c % NSTAGE) * STAGEB;
#pragma unroll
        for (int ks = 0; ks < 4; ks++) {
            uint32_t koff = (uint32_t)(ks << 5);   // 16 fp16 = 32 bytes per k-step
            uint32_t ar[2][4];
#pragma unroll
            for (int mt = 0; mt < 2; mt++)
                ldm_x4(ar[mt], st + a_off + (uint32_t)(mt * 16) * LDB + koff);
            uint32_t br[8][2];
#pragma unroll
            for (int jj = 0; jj < 4; jj++) {
                uint32_t r4[4];
                ldm_x4(r4, st + MATB + b_off + (uint32_t)(jj * 16) * LDB + koff);
                br[jj*2][0] = r4[0]; br[jj*2][1] = r4[1];
                br[jj*2+1][0] = r4[2]; br[jj*2+1][1] = r4[3];
            }
#pragma unroll
            for (int mt = 0; mt < 2; mt++)
#pragma unroll
                for (int nt = 0; nt < 8; nt++)
                    mma_fp16(acc[mt][nt], ar[mt], br[nt]);
        }
    }

#pragma unroll
    for (int mt = 0; mt < 2; mt++)
#pragma unroll
        for (int nt = 0; nt < 8; nt++) {
            int col = bn + warp_n * 64 + nt * 8 + (lane & 3) * 2;
            int r0 = bm + warp_m * 32 + mt * 16 + (lane >> 2);
#pragma unroll
            for (int hr = 0; hr < 2; hr++) {
                int m = r0 + hr * 8;
                float v0 = acc[mt][nt][hr*2+0], v1 = acc[mt][nt][hr*2+1];
                size_t off = (size_t)m * N + col;
                if (EPI == EPI_GELU) {
                    float2 bb = *reinterpret_cast<const float2*>(&bias[col]);
                    v0 += bb.x; v1 += bb.y;
                    const float is2 = 0.70710678118654752f;
                    v0 = 0.5f * v0 * (1.f + erff(v0 * is2));
                    v1 = 0.5f * v1 * (1.f + erff(v1 * is2));
                    __half2 hh = __halves2half2(__float2half(v0), __float2half(v1));
                    *reinterpret_cast<uint32_t*>(&Oh[off]) = *(uint32_t*)&hh;
                } else {
                    if (EPI == EPI_TANH) { v0 = tanhf(v0); v1 = tanhf(v1); }
                    else if (EPI == EPI_RES) {
                        float2 rr = *reinterpret_cast<const float2*>(&res[off]);
                        v0 += rr.x; v1 += rr.y;
                    } else if (EPI == EPI_RES_BIAS) {
                        float2 rr = *reinterpret_cast<const float2*>(&res[off]);
                        float2 bb = *reinterpret_cast<const float2*>(&bias[col]);
                        v0 += rr.x + bb.x; v1 += rr.y + bb.y;
                    }
                    *reinterpret_cast<float2*>(&C[off]) = make_float2(v0, v1);
                }
            }
        }
}

// ---------------- sd/pd gates ----------------
__global__ __launch_bounds__(256)
void sdpd_kernel(const float* __restrict__ Nmat,
                 const float* __restrict__ Wsd, const float* __restrict__ bsd,
                 const float* __restrict__ Wpd, const float* __restrict__ bpd,
                 float* __restrict__ SDo, float* __restrict__ PDo)
{
    const int RB = 128;
    __shared__ float As[16][RB];
    __shared__ float Ws[16][16];
    int tid = threadIdx.x, row = tid & 127, cg = tid >> 7;
    int m0 = blockIdx.x * RB;
    float acc[8];
#pragma unroll
    for (int j = 0; j < 8; j++) acc[j] = 0.f;
    int wk = tid >> 4, wc = tid & 15;
    for (int k0 = 0; k0 < DMc; k0 += 16) {
#pragma unroll
        for (int r = 0; r < 2; ++r) {
            int idx = tid + r * 256, ar = idx >> 2, c4 = (idx & 3) * 4;
            float4 v = *reinterpret_cast<const float4*>(&Nmat[(size_t)(m0+ar)*DMc + k0 + c4]);
            As[c4+0][ar]=v.x; As[c4+1][ar]=v.y; As[c4+2][ar]=v.z; As[c4+3][ar]=v.w;
        }
        Ws[wk][wc] = (wc < 8) ? Wsd[(size_t)(k0+wk)*Hc + wc] : Wpd[(size_t)(k0+wk)*Hc + wc - 8];
        __syncthreads();
#pragma unroll
        for (int kk = 0; kk < 16; ++kk) {
            float a = As[kk][row];
#pragma unroll
            for (int j = 0; j < 8; j++) acc[j] += a * Ws[kk][cg*8 + j];
        }
        __syncthreads();
    }
    float* outp = cg ? PDo : SDo;
    const float* bp = cg ? bpd : bsd;
#pragma unroll
    for (int j = 0; j < 8; j++) {
        float v = acc[j] + bp[j];
        outp[(size_t)(m0+row)*Hc + j] = 1.0f / (1.0f + expf(-v));
    }
}

// ---------------- scan (R6 smem version, 8-deep prefetch, fused P) ----------
__global__ __launch_bounds__(256)
void scan_kernel(const float* __restrict__ P,
                 const float* __restrict__ SDg, const float* __restrict__ PDg,
                 fp16* __restrict__ Y)
{
    int blk = blockIdx.x;
    int es = blk & 1, h = (blk >> 1) & 7, b = blk >> 4;
    int e_base = es * 32;
    int tid = threadIdx.x, e_local = tid & 31, dg = tid >> 5, d0 = dg * 8;

    __shared__ float s_vec[4][64];
    __shared__ float s_state[2][64];
    __shared__ float s_red[8][32];
    __shared__ float s_sp[2];

    float pair[8];
#pragma unroll
    for (int i = 0; i < 8; i++) pair[i] = 0.f;
    if (tid < 64) { s_state[0][tid] = 0.f; s_state[1][tid] = 0.f; }

    int grp = tid >> 6, lane64 = tid & 63;
    size_t inbase = ((size_t)b * Tc) * 2048 + (size_t)grp * 512 + (size_t)h * SDc + lane64;
    size_t sp_base = ((size_t)b * Tc) * Hc + h;
    size_t outbase = ((size_t)b * Tc) * INNERc + (size_t)h * SDc;

    const int PFD = 8;
    float pf[PFD], psd[PFD], ppd[PFD];
#pragma unroll
    for (int j = 0; j < PFD; j++) {
        pf[j] = P[inbase + (size_t)j * 2048];
        if (tid == 0) {
            psd[j] = SDg[sp_base + (size_t)j * Hc];
            ppd[j] = PDg[sp_base + (size_t)j * Hc];
        }
    }

    for (int t = 0; t < Tc; t += PFD) {
#pragma unroll
        for (int j = 0; j < PFD; j++) {
            int tt = t + j, p = tt & 1;
            s_vec[grp][lane64] = pf[j];
            if (tid == 0) { s_sp[0] = psd[j]; s_sp[1] = ppd[j]; }
            __syncthreads();
            if (tt + PFD < Tc) {
                pf[j] = P[inbase + (size_t)(tt + PFD) * 2048];
                if (tid == 0) {
                    size_t sb = sp_base + (size_t)(tt + PFD) * Hc;
                    psd[j] = SDg[sb]; ppd[j] = PDg[sb];
                }
            }
            float sdv = s_sp[0], pdv = s_sp[1];
            float be = s_vec[1][e_base + e_local];
            float ompd_be = (1.f - pdv) * be;
            float qrv = s_vec[3][e_base + e_local];
            float acc = 0.f;
#pragma unroll
            for (int i = 0; i < 8; i++) {
                int d = d0 + i;
                float ps = s_state[p][d];
                pair[i] = pdv * pair[i] + ompd_be * ps;
                acc += pair[i] * s_vec[2][d];
            }
            s_red[dg][e_local] = acc;
            if (tid < 64)
                s_state[p ^ 1][tid] = sdv * s_state[p][tid] + (1.f - sdv) * s_vec[0][tid];
            __syncthreads();
            if (dg == 0) {
                float left = 0.f;
#pragma unroll
                for (int g2 = 0; g2 < 8; ++g2) left += s_red[g2][e_local];
                Y[outbase + (size_t)tt * INNERc + e_base + e_local] =
                    __float2half(left * qrv);
            }
        }
    }
}

// ---------------- launch ----------------
static float* symf(const void* s) { void* p = 0; cudaGetSymbolAddress(&p, s); return (float*)p; }
static fp16*  symh(const void* s) { void* p = 0; cudaGetSymbolAddress(&p, s); return (fp16*)p; }

extern "C" void kernel_launch(void* const* d_in, const int* in_sizes, int n_in,
                              void* d_out, int out_size)
{
    const float* x    = (const float*)d_in[0];
    const float* ln_g = (const float*)d_in[1];
    const float* ln_b = (const float*)d_in[2];
    const float* ffn_g= (const float*)d_in[3];
    const float* ffn_b= (const float*)d_in[4];
    const float* Wa   = (const float*)d_in[5];
    const float* Wb   = (const float*)d_in[6];
    const float* Wql  = (const float*)d_in[7];
    const float* Wqr  = (const float*)d_in[8];
    const float* Wsd  = (const float*)d_in[9];
    const float* bsd  = (const float*)d_in[10];
    const float* Wpd  = (const float*)d_in[11];
    const float* bpd  = (const float*)d_in[12];
    const float* Wout = (const float*)d_in[13];
    const float* W1   = (const float*)d_in[14];
    const float* b1   = (const float*)d_in[15];
    const float* W2   = (const float*)d_in[16];
    const float* b2   = (const float*)d_in[17];
    float* out = (float*)d_out;

    cudaFuncSetAttribute(mma_gemm<EPI_TANH>, cudaFuncAttributeMaxDynamicSharedMemorySize, SMEM_DYN);
    cudaFuncSetAttribute(mma_gemm<EPI_RES>, cudaFuncAttributeMaxDynamicSharedMemorySize, SMEM_DYN);
    cudaFuncSetAttribute(mma_gemm<EPI_GELU>, cudaFuncAttributeMaxDynamicSharedMemorySize, SMEM_DYN);
    cudaFuncSetAttribute(mma_gemm<EPI_RES_BIAS>, cudaFuncAttributeMaxDynamicSharedMemorySize, SMEM_DYN);

    dim3 tb(32, 8);
    // launches 1-3
    tsplit4_kernel<<<dim3(INNERc/32, DMc/32, 4), tb>>>(Wa, Wb, Wql, Wqr, symh(g_wp));
    ln_h_kernel<true><<<Mrows, 256>>>(x, ln_g, ln_b, symf(g_n), symh(g_nh));
    tsplit_kernel<<<dim3(DMc/32, INNERc/32), tb>>>(Wout, symh(g_wo), INNERc, DMc);
    // launch 4 <- profiled
    {
        dim3 grid(2048/128, Mrows/128);
        mma_gemm<EPI_TANH><<<grid, 256, SMEM_DYN>>>(symh(g_nh), symh(g_wp),
            symf(g_proj), nullptr, nullptr, nullptr, Mrows, 2048, DMc);
    }
    tsplit_kernel<<<dim3(HIDc/32, DMc/32), tb>>>(W1, symh(g_w1), DMc, HIDc);
    tsplit_kernel<<<dim3(DMc/32, HIDc/32), tb>>>(W2, symh(g_w2), HIDc, DMc);

    sdpd_kernel<<<Mrows/128, 256>>>(symf(g_n), Wsd, bsd, Wpd, bpd, symf(g_sd), symf(g_pd));

    scan_kernel<<<Bc*Hc*2, 256>>>(symf(g_proj), symf(g_sd), symf(g_pd), symh(g_ys));

    {   // h = x + ys @ Wout
        dim3 grid(DMc/128, Mrows/128);
        mma_gemm<EPI_RES><<<grid, 256, SMEM_DYN>>>(symh(g_ys), symh(g_wo),
            symf(g_h), nullptr, x, nullptr, Mrows, DMc, INNERc);
    }

    ln_h_kernel<false><<<Mrows, 256>>>(symf(g_h), ffn_g, ffn_b, nullptr, symh(g_fin));

    {   // mid = gelu(fin @ W1 + b1) -> fp16
        dim3 grid(HIDc/128, Mrows/128);
        mma_gemm<EPI_GELU><<<grid, 256, SMEM_DYN>>>(symh(g_fin), symh(g_w1),
            nullptr, symh(g_mid), nullptr, b1, Mrows, HIDc, DMc);
    }

    {   // out = h + mid @ W2 + b2
        dim3 grid(DMc/128, Mrows/128);
        mma_gemm<EPI_RES_BIAS><<<grid, 256, SMEM_DYN>>>(symh(g_mid), symh(g_w2),
            out, nullptr, symf(g_h), b2, Mrows, DMc, HIDc);
    }
}

// round 10
// speedup vs baseline: 1.0707x; 1.0707x over previous
#include <cuda_runtime.h>
#include <cuda_fp16.h>
#include <math.h>
#include <stdint.h>

#define Bc 8
#define Tc 2048
#define DMc 1024
#define Hc 8
#define SDc 64
#define INNERc 512
#define HIDc 4096
#define Mrows (Bc * Tc)

typedef __half fp16;

__device__ __align__(256) float g_n  [(size_t)Mrows * DMc];
__device__ __align__(256) fp16  g_nh [(size_t)Mrows * DMc];
__device__ __align__(256) float g_proj[(size_t)Mrows * 2048]; // a|b|ql|qr fused
__device__ __align__(256) float g_sd [(size_t)Mrows * Hc];
__device__ __align__(256) float g_pd [(size_t)Mrows * Hc];
__device__ __align__(256) fp16  g_ys [(size_t)Mrows * INNERc];
__device__ __align__(256) float g_h  [(size_t)Mrows * DMc];
__device__ __align__(256) fp16  g_fin[(size_t)Mrows * DMc];
__device__ __align__(256) fp16  g_mid[(size_t)Mrows * HIDc];
__device__ __align__(256) fp16 g_wp[2048*DMc];
__device__ __align__(256) fp16 g_wo[DMc*INNERc];
__device__ __align__(256) fp16 g_w1[HIDc*DMc];
__device__ __align__(256) fp16 g_w2[DMc*HIDc];

// ---------------- helpers ----------------
__device__ __forceinline__ uint32_t smem_u32(const void* p) {
    return (uint32_t)__cvta_generic_to_shared(p);
}
__device__ __forceinline__ void cp16(uint32_t dst, const void* src) {
    asm volatile("cp.async.cg.shared.global [%0], [%1], 16;\n" :: "r"(dst), "l"(src));
}
__device__ __forceinline__ void cp_commit() { asm volatile("cp.async.commit_group;\n"); }
template <int NN> __device__ __forceinline__ void cp_wait() {
    asm volatile("cp.async.wait_group %0;\n" :: "n"(NN));
}
__device__ __forceinline__ void ldm_x4(uint32_t* r, uint32_t addr) {
    asm volatile("ldmatrix.sync.aligned.m8n8.x4.shared.b16 {%0,%1,%2,%3}, [%4];"
        : "=r"(r[0]), "=r"(r[1]), "=r"(r[2]), "=r"(r[3]) : "r"(addr));
}
__device__ __forceinline__ void mma_fp16(float* d, const uint32_t* a, const uint32_t* b) {
    asm volatile("mma.sync.aligned.m16n8k16.row.col.f32.f16.f16.f32 "
        "{%0,%1,%2,%3},{%4,%5,%6,%7},{%8,%9},{%0,%1,%2,%3};"
        : "+f"(d[0]), "+f"(d[1]), "+f"(d[2]), "+f"(d[3])
        : "r"(a[0]), "r"(a[1]), "r"(a[2]), "r"(a[3]), "r"(b[0]), "r"(b[1]));
}

// ---------------- LN (+optional fp32 out) + fp16 out ----------------
template <bool F32OUT>
__global__ void ln_h_kernel(const float* __restrict__ X,
                            const float* __restrict__ gam,
                            const float* __restrict__ bet,
                            float* __restrict__ Of, fp16* __restrict__ Oh)
{
    int row = blockIdx.x, tid = threadIdx.x;
    const float4* xr = reinterpret_cast<const float4*>(X + (size_t)row * DMc);
    float4 v = xr[tid];
    float s = v.x + v.y + v.z + v.w;
    float q = v.x*v.x + v.y*v.y + v.z*v.z + v.w*v.w;
    int lane = tid & 31, wid = tid >> 5;
#pragma unroll
    for (int o = 16; o; o >>= 1) {
        s += __shfl_xor_sync(0xffffffffu, s, o);
        q += __shfl_xor_sync(0xffffffffu, q, o);
    }
    __shared__ float rs[8], rq[8];
    if (!lane) { rs[wid] = s; rq[wid] = q; }
    __syncthreads();
    if (tid == 0) {
        float S = 0.f, Q = 0.f;
#pragma unroll
        for (int i = 0; i < 8; i++) { S += rs[i]; Q += rq[i]; }
        rs[0] = S; rq[0] = Q;
    }
    __syncthreads();
    float mu = rs[0] * (1.0f / DMc);
    float var = rq[0] * (1.0f / DMc) - mu * mu;
    float rstd = rsqrtf(var + 1e-5f);
    const float4 gg = reinterpret_cast<const float4*>(gam)[tid];
    const float4 bb = reinterpret_cast<const float4*>(bet)[tid];
    float o[4];
    o[0] = (v.x-mu)*rstd*gg.x + bb.x; o[1] = (v.y-mu)*rstd*gg.y + bb.y;
    o[2] = (v.z-mu)*rstd*gg.z + bb.z; o[3] = (v.w-mu)*rstd*gg.w + bb.w;
    size_t off = (size_t)row * DMc + tid * 4;
    if (F32OUT)
        *reinterpret_cast<float4*>(Of + off) = make_float4(o[0], o[1], o[2], o[3]);
    __half2 h0 = __halves2half2(__float2half(o[0]), __float2half(o[1]));
    __half2 h1 = __halves2half2(__float2half(o[2]), __float2half(o[3]));
    *reinterpret_cast<uint2*>(Oh + off) = make_uint2(*(uint32_t*)&h0, *(uint32_t*)&h1);
}

// ---------------- weight transpose: W[K,N] f32 -> [N,K] fp16 ----------------
__global__ void tsplit_kernel(const float* __restrict__ W,
                              fp16* __restrict__ Oh, int K, int N)
{
    __shared__ float t[32][33];
    int n0 = blockIdx.x * 32, k0 = blockIdx.y * 32;
    int tx = threadIdx.x, ty = threadIdx.y;  // 32 x 8
#pragma unroll
    for (int j = 0; j < 32; j += 8)
        t[ty + j][tx] = W[(size_t)(k0 + ty + j) * N + n0 + tx];
    __syncthreads();
#pragma unroll
    for (int j = 0; j < 32; j += 8)
        Oh[(size_t)(n0 + ty + j) * K + k0 + tx] = __float2half(t[tx][ty + j]);
}

// fused: 4 projection weights [1024,512] -> packed [2048,1024]
__global__ void tsplit4_kernel(const float* __restrict__ Wa, const float* __restrict__ Wb,
                               const float* __restrict__ Wql, const float* __restrict__ Wqr,
                               fp16* __restrict__ Oh)
{
    int z = blockIdx.z;
    const float* W = (z == 0) ? Wa : (z == 1) ? Wb : (z == 2) ? Wql : Wqr;
    __shared__ float t[32][33];
    int n0 = blockIdx.x * 32, k0 = blockIdx.y * 32;
    int tx = threadIdx.x, ty = threadIdx.y;
#pragma unroll
    for (int j = 0; j < 32; j += 8)
        t[ty + j][tx] = W[(size_t)(k0 + ty + j) * INNERc + n0 + tx];
    __syncthreads();
#pragma unroll
    for (int j = 0; j < 32; j += 8)
        Oh[(size_t)(z * INNERc + n0 + ty + j) * DMc + k0 + tx] = __float2half(t[tx][ty + j]);
}

// ---------------- mma.sync fp16 GEMM: tile 128x128x64, 3-stage, 1 sync/iter --
enum { EPI_TANH = 1, EPI_RES = 2, EPI_GELU = 3, EPI_RES_BIAS = 4 };
#define LDB 144u           // 64 fp16 = 128B + 16B pad
#define MATB 18432u        // 128 rows * 144B
#define STAGEB 36864u
#define NSTAGE 3
#define SMEM_DYN (3 * 36864)

template <int EPI>
__global__ __launch_bounds__(256)
void mma_gemm(const fp16* __restrict__ A, const fp16* __restrict__ B,
              float* __restrict__ C, fp16* __restrict__ Oh,
              const float* __restrict__ res, const float* __restrict__ bias,
              int M, int N, int K)
{
    extern __shared__ char smraw[];
    uint32_t sbase = smem_u32(smraw);
    int tid = threadIdx.x, lane = tid & 31, wid = tid >> 5;
    int warp_m = wid & 3, warp_n = wid >> 2;
    int bm = blockIdx.y * 128, bn = blockIdx.x * 128;

    float acc[2][8][4];
#pragma unroll
    for (int a = 0; a < 2; a++)
#pragma unroll
        for (int b = 0; b < 8; b++)
#pragma unroll
            for (int c = 0; c < 4; c++) acc[a][b][c] = 0.f;

    auto load_stage = [&](int c) {
        int k0 = c * 64;
        uint32_t st = sbase + (uint32_t)(c % NSTAGE) * STAGEB;
#pragma unroll
        for (int i = 0; i < 8; i++) {
            int id = tid + i * 256;
            int mat = id >> 10, rem = id & 1023;
            int r = rem >> 3, g = rem & 7;
            const fp16* src = mat ? B : A;
            int row = (mat ? bn : bm) + r;
            cp16(st + (uint32_t)mat * MATB + (uint32_t)r * LDB + (uint32_t)g * 16u,
                 src + (size_t)row * K + k0 + g * 8);
        }
        cp_commit();
    };

    int NC = K / 64;
    load_stage(0);
    load_stage(1);

    uint32_t a_off = (uint32_t)(warp_m * 32 + (lane & 15)) * LDB + (uint32_t)((lane >> 4) << 4);
    int bg = lane >> 3, bt = lane & 7;
    uint32_t b_off = (uint32_t)(warp_n * 64 + ((bg >> 1) << 3) + bt) * LDB + (uint32_t)((bg & 1) << 4);

    for (int c = 0; c < NC; c++) {
        cp_wait<1>();
        __syncthreads();
        if (c + 2 < NC) load_stage(c + 2);
        uint32_t st = sbase + (uint32_t)(c % NSTAGE) * STAGEB;
#pragma unroll
        for (int ks = 0; ks < 4; ks++) {
            uint32_t koff = (uint32_t)(ks << 5);
            uint32_t ar[2][4];
#pragma unroll
            for (int mt = 0; mt < 2; mt++)
                ldm_x4(ar[mt], st + a_off + (uint32_t)(mt * 16) * LDB + koff);
            uint32_t br[8][2];
#pragma unroll
            for (int jj = 0; jj < 4; jj++) {
                uint32_t r4[4];
                ldm_x4(r4, st + MATB + b_off + (uint32_t)(jj * 16) * LDB + koff);
                br[jj*2][0] = r4[0]; br[jj*2][1] = r4[1];
                br[jj*2+1][0] = r4[2]; br[jj*2+1][1] = r4[3];
            }
#pragma unroll
            for (int mt = 0; mt < 2; mt++)
#pragma unroll
                for (int nt = 0; nt < 8; nt++)
                    mma_fp16(acc[mt][nt], ar[mt], br[nt]);
        }
    }

#pragma unroll
    for (int mt = 0; mt < 2; mt++)
#pragma unroll
        for (int nt = 0; nt < 8; nt++) {
            int col = bn + warp_n * 64 + nt * 8 + (lane & 3) * 2;
            int r0 = bm + warp_m * 32 + mt * 16 + (lane >> 2);
#pragma unroll
            for (int hr = 0; hr < 2; hr++) {
                int m = r0 + hr * 8;
                float v0 = acc[mt][nt][hr*2+0], v1 = acc[mt][nt][hr*2+1];
                size_t off = (size_t)m * N + col;
                if (EPI == EPI_GELU) {
                    float2 bb = *reinterpret_cast<const float2*>(&bias[col]);
                    v0 += bb.x; v1 += bb.y;
                    const float is2 = 0.70710678118654752f;
                    v0 = 0.5f * v0 * (1.f + erff(v0 * is2));
                    v1 = 0.5f * v1 * (1.f + erff(v1 * is2));
                    __half2 hh = __halves2half2(__float2half(v0), __float2half(v1));
                    *reinterpret_cast<uint32_t*>(&Oh[off]) = *(uint32_t*)&hh;
                } else {
                    if (EPI == EPI_TANH) { v0 = tanhf(v0); v1 = tanhf(v1); }
                    else if (EPI == EPI_RES) {
                        float2 rr = *reinterpret_cast<const float2*>(&res[off]);
                        v0 += rr.x; v1 += rr.y;
                    } else if (EPI == EPI_RES_BIAS) {
                        float2 rr = *reinterpret_cast<const float2*>(&res[off]);
                        float2 bb = *reinterpret_cast<const float2*>(&bias[col]);
                        v0 += rr.x + bb.x; v1 += rr.y + bb.y;
                    }
                    *reinterpret_cast<float2*>(&C[off]) = make_float2(v0, v1);
                }
            }
        }
}

// ---------------- sd/pd gates ----------------
__global__ __launch_bounds__(256)
void sdpd_kernel(const float* __restrict__ Nmat,
                 const float* __restrict__ Wsd, const float* __restrict__ bsd,
                 const float* __restrict__ Wpd, const float* __restrict__ bpd,
                 float* __restrict__ SDo, float* __restrict__ PDo)
{
    const int RB = 128;
    __shared__ float As[16][RB];
    __shared__ float Ws[16][16];
    int tid = threadIdx.x, row = tid & 127, cg = tid >> 7;
    int m0 = blockIdx.x * RB;
    float acc[8];
#pragma unroll
    for (int j = 0; j < 8; j++) acc[j] = 0.f;
    int wk = tid >> 4, wc = tid & 15;
    for (int k0 = 0; k0 < DMc; k0 += 16) {
#pragma unroll
        for (int r = 0; r < 2; ++r) {
            int idx = tid + r * 256, ar = idx >> 2, c4 = (idx & 3) * 4;
            float4 v = *reinterpret_cast<const float4*>(&Nmat[(size_t)(m0+ar)*DMc + k0 + c4]);
            As[c4+0][ar]=v.x; As[c4+1][ar]=v.y; As[c4+2][ar]=v.z; As[c4+3][ar]=v.w;
        }
        Ws[wk][wc] = (wc < 8) ? Wsd[(size_t)(k0+wk)*Hc + wc] : Wpd[(size_t)(k0+wk)*Hc + wc - 8];
        __syncthreads();
#pragma unroll
        for (int kk = 0; kk < 16; ++kk) {
            float a = As[kk][row];
#pragma unroll
            for (int j = 0; j < 8; j++) acc[j] += a * Ws[kk][cg*8 + j];
        }
        __syncthreads();
    }
    float* outp = cg ? PDo : SDo;
    const float* bp = cg ? bpd : bsd;
#pragma unroll
    for (int j = 0; j < 8; j++) {
        float v = acc[j] + bp[j];
        outp[(size_t)(m0+row)*Hc + j] = 1.0f / (1.0f + expf(-v));
    }
}

// ---------------- scan: batch-8 smem staging, warp-autonomous compute --------
// grid 128 = es(2) x h(8) x b(8); 256 threads = 8 warps x (8 dg x 4 eidx).
// One __syncthreads per 8 steps; state replicated per warp; shfl d-reduction.
__global__ __launch_bounds__(256)
void scan_kernel(const float* __restrict__ P,
                 const float* __restrict__ SDg, const float* __restrict__ PDg,
                 fp16* __restrict__ Y)
{
    int blk = blockIdx.x;
    int es = blk & 1, h = (blk >> 1) & 7, b = blk >> 4;
    int tid = threadIdx.x, w = tid >> 5, lane = tid & 31;
    int eidx = lane & 3, dg = lane >> 2;
    int e_loc = es * 32 + w * 4 + eidx;

    __shared__ float s_a [2][8][68];   // +4 swizzle pad at d>=32
    __shared__ float s_ql[2][8][68];
    __shared__ float s_b [2][8][32];
    __shared__ float s_qr[2][8][32];
    __shared__ float s_sp[2][8][2];

    size_t Pbase = ((size_t)b * Tc) * 2048 + (size_t)h * SDc;
    size_t spb   = ((size_t)b * Tc) * Hc + h;
    size_t outb  = ((size_t)b * Tc) * INNERc + (size_t)h * SDc + e_loc;

    auto load_batch = [&](int t0, float* r) {
#pragma unroll
        for (int i = 0; i < 7; i++) {
            int f = tid + i * 256;
            float v = 0.f;
            if (f < 512) {
                int j = f >> 6, d = f & 63;
                v = P[Pbase + (size_t)(t0 + j) * 2048 + d];
            } else if (f < 1024) {
                int g = f - 512; int j = g >> 6, d = g & 63;
                v = P[Pbase + (size_t)(t0 + j) * 2048 + 1024 + d];
            } else if (f < 1280) {
                int g = f - 1024; int j = g >> 5, e = g & 31;
                v = P[Pbase + (size_t)(t0 + j) * 2048 + 512 + es * 32 + e];
            } else if (f < 1536) {
                int g = f - 1280; int j = g >> 5, e = g & 31;
                v = P[Pbase + (size_t)(t0 + j) * 2048 + 1536 + es * 32 + e];
            } else if (f < 1552) {
                int g = f - 1536; int j = g >> 1;
                v = (g & 1) ? PDg[spb + (size_t)(t0 + j) * Hc]
                            : SDg[spb + (size_t)(t0 + j) * Hc];
            }
            r[i] = v;
        }
    };
    auto store_batch = [&](int buf, const float* r) {
#pragma unroll
        for (int i = 0; i < 7; i++) {
            int f = tid + i * 256;
            if (f < 512) {
                int j = f >> 6, d = f & 63;
                s_a[buf][j][d + ((d >> 5) << 2)] = r[i];
            } else if (f < 1024) {
                int g = f - 512; int j = g >> 6, d = g & 63;
                s_ql[buf][j][d + ((d >> 5) << 2)] = r[i];
            } else if (f < 1280) {
                int g = f - 1024;
                s_b[buf][g >> 5][g & 31] = r[i];
            } else if (f < 1536) {
                int g = f - 1280;
                s_qr[buf][g >> 5][g & 31] = r[i];
            } else if (f < 1552) {
                int g = f - 1536;
                s_sp[buf][g >> 1][g & 1] = r[i];
            }
        }
    };

    float pair[8], state[8];
#pragma unroll
    for (int i = 0; i < 8; i++) { pair[i] = 0.f; state[i] = 0.f; }

    float rr[2][7];
    {
        float ra[7];
        load_batch(0, ra);
        store_batch(0, ra);
    }
    load_batch(8, rr[0]);
    __syncthreads();

    int sbidx = dg * 8 + ((dg >> 2) << 2);   // swizzled base for this lane's d-group

    for (int k = 0; k < Tc / 8; k++) {
        int buf = k & 1;
        int t0 = k * 8;
        if (t0 + 16 < Tc) load_batch(t0 + 16, rr[buf ^ 1]);
        if (t0 + 8 < Tc) store_batch(buf ^ 1, rr[buf]);
#pragma unroll
        for (int j = 0; j < 8; j++) {
            float sd = s_sp[buf][j][0], pd = s_sp[buf][j][1];
            float bv = s_b[buf][j][w * 4 + eidx];
            float qr = s_qr[buf][j][w * 4 + eidx];
            float ompd_b = (1.f - pd) * bv;
            float acc = 0.f;
#pragma unroll
            for (int i = 0; i < 8; i++) {
                float qlv = s_ql[buf][j][sbidx + i];
                pair[i] = pd * pair[i] + ompd_b * state[i];
                acc += pair[i] * qlv;
            }
            float oms = 1.f - sd;
#pragma unroll
            for (int i = 0; i < 8; i++)
                state[i] = sd * state[i] + oms * s_a[buf][j][sbidx + i];
            acc += __shfl_xor_sync(0xffffffffu, acc, 4);
            acc += __shfl_xor_sync(0xffffffffu, acc, 8);
            acc += __shfl_xor_sync(0xffffffffu, acc, 16);
            if (dg == 0)
                Y[outb + (size_t)(t0 + j) * INNERc] = __float2half(acc * qr);
        }
        __syncthreads();
    }
}

// ---------------- launch ----------------
static float* symf(const void* s) { void* p = 0; cudaGetSymbolAddress(&p, s); return (float*)p; }
static fp16*  symh(const void* s) { void* p = 0; cudaGetSymbolAddress(&p, s); return (fp16*)p; }

extern "C" void kernel_launch(void* const* d_in, const int* in_sizes, int n_in,
                              void* d_out, int out_size)
{
    const float* x    = (const float*)d_in[0];
    const float* ln_g = (const float*)d_in[1];
    const float* ln_b = (const float*)d_in[2];
    const float* ffn_g= (const float*)d_in[3];
    const float* ffn_b= (const float*)d_in[4];
    const float* Wa   = (const float*)d_in[5];
    const float* Wb   = (const float*)d_in[6];
    const float* Wql  = (const float*)d_in[7];
    const float* Wqr  = (const float*)d_in[8];
    const float* Wsd  = (const float*)d_in[9];
    const float* bsd  = (const float*)d_in[10];
    const float* Wpd  = (const float*)d_in[11];
    const float* bpd  = (const float*)d_in[12];
    const float* Wout = (const float*)d_in[13];
    const float* W1   = (const float*)d_in[14];
    const float* b1   = (const float*)d_in[15];
    const float* W2   = (const float*)d_in[16];
    const float* b2   = (const float*)d_in[17];
    float* out = (float*)d_out;

    cudaFuncSetAttribute(mma_gemm<EPI_TANH>, cudaFuncAttributeMaxDynamicSharedMemorySize, SMEM_DYN);
    cudaFuncSetAttribute(mma_gemm<EPI_RES>, cudaFuncAttributeMaxDynamicSharedMemorySize, SMEM_DYN);
    cudaFuncSetAttribute(mma_gemm<EPI_GELU>, cudaFuncAttributeMaxDynamicSharedMemorySize, SMEM_DYN);
    cudaFuncSetAttribute(mma_gemm<EPI_RES_BIAS>, cudaFuncAttributeMaxDynamicSharedMemorySize, SMEM_DYN);

    dim3 tb(32, 8);
    // launches 1-3
    tsplit4_kernel<<<dim3(INNERc/32, DMc/32, 4), tb>>>(Wa, Wb, Wql, Wqr, symh(g_wp));
    ln_h_kernel<true><<<Mrows, 256>>>(x, ln_g, ln_b, symf(g_n), symh(g_nh));
    tsplit_kernel<<<dim3(DMc/32, INNERc/32), tb>>>(Wout, symh(g_wo), INNERc, DMc);
    // launch 4 <- profiled
    {
        dim3 grid(2048/128, Mrows/128);
        mma_gemm<EPI_TANH><<<grid, 256, SMEM_DYN>>>(symh(g_nh), symh(g_wp),
            symf(g_proj), nullptr, nullptr, nullptr, Mrows, 2048, DMc);
    }
    tsplit_kernel<<<dim3(HIDc/32, DMc/32), tb>>>(W1, symh(g_w1), DMc, HIDc);
    tsplit_kernel<<<dim3(DMc/32, HIDc/32), tb>>>(W2, symh(g_w2), HIDc, DMc);

    sdpd_kernel<<<Mrows/128, 256>>>(symf(g_n), Wsd, bsd, Wpd, bpd, symf(g_sd), symf(g_pd));

    scan_kernel<<<Bc*Hc*2, 256>>>(symf(g_proj), symf(g_sd), symf(g_pd), symh(g_ys));

    {   // h = x + ys @ Wout
        dim3 grid(DMc/128, Mrows/128);
        mma_gemm<EPI_RES><<<grid, 256, SMEM_DYN>>>(symh(g_ys), symh(g_wo),
            symf(g_h), nullptr, x, nullptr, Mrows, DMc, INNERc);
    }

    ln_h_kernel<false><<<Mrows, 256>>>(symf(g_h), ffn_g, ffn_b, nullptr, symh(g_fin));

    {   // mid = gelu(fin @ W1 + b1) -> fp16
        dim3 grid(HIDc/128, Mrows/128);
        mma_gemm<EPI_GELU><<<grid, 256, SMEM_DYN>>>(symh(g_fin), symh(g_w1),
            nullptr, symh(g_mid), nullptr, b1, Mrows, HIDc, DMc);
    }

    {   // out = h + mid @ W2 + b2
        dim3 grid(DMc/128, Mrows/128);
        mma_gemm<EPI_RES_BIAS><<<grid, 256, SMEM_DYN>>>(symh(g_mid), symh(g_w2),
            out, nullptr, symf(g_h), b2, Mrows, DMc, HIDc);
    }
}